// round 1
// baseline (speedup 1.0000x reference)
#include <cuda_runtime.h>
#include <cstdint>

#define N_NODES 100000
#define N_EDGES 1600000
#define NF 128
#define NH 128
#define NC 10
#define NG 64

// ---------------- scratch (static __device__, no allocation) ----------------
__device__ float d_deg[N_NODES];
__device__ float d_dis[N_NODES];
__device__ float d_cnt[NG];
__device__ float d_invc[NG];
__device__ float d_t1[N_NODES * NG];   // 25.6 MB, L2-resident
__device__ float d_t2[N_NODES * NG];   // 25.6 MB, L2-resident
__device__ float d_s[NG];              // colsum(t1)  -> b2 term
__device__ float d_c1[NG];             // colsum(t2)  -> b1 term
__device__ float d_G[NG * NF];         // t2^T x
__device__ float d_M1[NG * NH];        // G @ W1
__device__ int   d_is64;

// ---------------- helpers ----------------
__device__ __forceinline__ int read_idx(const void* p, long long i, int is64) {
    return is64 ? (int)((const long long*)p)[i] : ((const int*)p)[i];
}

__device__ __forceinline__ void red4(float* addr, float x, float y, float z, float w) {
    asm volatile("red.global.add.v4.f32 [%0], {%1,%2,%3,%4};"
                 :: "l"(addr), "f"(x), "f"(y), "f"(z), "f"(w) : "memory");
}

// Detect whether index arrays are int64 (high words of nonneg <2^31 values are 0)
__global__ void k_detect(const void* ei) {
    const int* p = (const int*)ei;
    unsigned ok = __ballot_sync(0xFFFFFFFFu, p[2 * threadIdx.x + 1] == 0);
    if (threadIdx.x == 0) d_is64 = (ok == 0xFFFFFFFFu) ? 1 : 0;
}

// deg[col]+=1 per edge; deg[i]+=1 self-loop; cnt[batch[i]]+=1
__global__ void k_deg(const void* ei, const void* batch) {
    int i = blockIdx.x * blockDim.x + threadIdx.x;
    int is64 = d_is64;
    if (i < N_EDGES) {
        int c = read_idx(ei, (long long)N_EDGES + i, is64);  // col = second row
        atomicAdd(&d_deg[c], 1.0f);
    } else if (i < N_EDGES + N_NODES) {
        int n = i - N_EDGES;
        atomicAdd(&d_deg[n], 1.0f);
        int g = read_idx(batch, n, is64);
        atomicAdd(&d_cnt[g], 1.0f);
    }
}

__global__ void k_dis() {
    int i = blockIdx.x * blockDim.x + threadIdx.x;
    if (i < N_NODES) {
        float d = d_deg[i];
        d_dis[i] = (d > 0.0f) ? rsqrtf(fmaxf(d, 1e-12f)) : 0.0f;
    }
    if (i < NG) d_invc[i] = 1.0f / fmaxf(d_cnt[i], 1.0f);
}

// t1[r, batch[c]] += dis[r]*dis[c]*invc[batch[c]]   (1 atomic per edge!)
__global__ void k_t1(const void* ei, const void* batch) {
    int i = blockIdx.x * blockDim.x + threadIdx.x;
    int is64 = d_is64;
    if (i < N_EDGES) {
        int r = read_idx(ei, i, is64);
        int c = read_idx(ei, (long long)N_EDGES + i, is64);
        int g = read_idx(batch, c, is64);
        float v = d_dis[r] * d_dis[c] * d_invc[g];
        atomicAdd(&d_t1[r * NG + g], v);
    } else if (i < N_EDGES + N_NODES) {
        int n = i - N_EDGES;
        int g = read_idx(batch, n, is64);
        float ds = d_dis[n];
        atomicAdd(&d_t1[n * NG + g], ds * ds * d_invc[g]);
    }
}

// t2[r] += norm * t1[c]  (64-wide, 8 threads/edge, v4 reduction atomics)
__global__ void k_t2(const void* ei) {
    int t = blockIdx.x * blockDim.x + threadIdx.x;
    int item = t >> 3;
    int lane = t & 7;
    if (item >= N_EDGES + N_NODES) return;
    int is64 = d_is64;
    int r, c;
    if (item < N_EDGES) {
        r = read_idx(ei, item, is64);
        c = read_idx(ei, (long long)N_EDGES + item, is64);
    } else {
        r = c = item - N_EDGES;
    }
    float nv = d_dis[r] * d_dis[c];
    const float4* src = (const float4*)(d_t1 + (size_t)c * NG) + lane * 2;
    float4 a = src[0];
    float4 b = src[1];
    float* dst = d_t2 + (size_t)r * NG + lane * 8;
    red4(dst,     a.x * nv, a.y * nv, a.z * nv, a.w * nv);
    red4(dst + 4, b.x * nv, b.y * nv, b.z * nv, b.w * nv);
}

// s[g] = sum_i t1[i,g]
__global__ void k_s() {
    __shared__ float sl[NG];
    if (threadIdx.x < NG) sl[threadIdx.x] = 0.0f;
    __syncthreads();
    int stride = gridDim.x * blockDim.x;
    for (int j = blockIdx.x * blockDim.x + threadIdx.x; j < N_NODES * NG; j += stride)
        atomicAdd(&sl[j & (NG - 1)], d_t1[j]);
    __syncthreads();
    if (threadIdx.x < NG) atomicAdd(&d_s[threadIdx.x], sl[threadIdx.x]);
}

// G = t2^T x  [64 x 128] with per-block register tiles; also c1 = colsum(t2)
__global__ void k_G(const float* __restrict__ x) {
    __shared__ float sT2[8 * NG];
    __shared__ float sX[8 * NF];
    int tid = threadIdx.x;                 // 256 threads
    int g0 = (tid >> 3) * 2;               // 2 graphs per thread
    int f0 = (tid & 7) * 16;               // 16 features per thread
    float ra[2][16];
#pragma unroll
    for (int a = 0; a < 2; a++)
#pragma unroll
        for (int b = 0; b < 16; b++) ra[a][b] = 0.0f;
    float c1a = 0.0f, c1b = 0.0f;

    int per = (N_NODES + gridDim.x - 1) / gridDim.x;
    int nb = blockIdx.x * per;
    int ne = min(nb + per, N_NODES);

    for (int base = nb; base < ne; base += 8) {
        int nstage = min(8, ne - base);
        __syncthreads();
        const float4* t2p = (const float4*)(d_t2 + (size_t)base * NG);
        for (int j = tid; j < nstage * (NG / 4); j += 256) ((float4*)sT2)[j] = t2p[j];
        const float4* xp = (const float4*)(x + (size_t)base * NF);
        for (int j = tid; j < nstage * (NF / 4); j += 256) ((float4*)sX)[j] = xp[j];
        __syncthreads();
        for (int j = 0; j < nstage; j++) {
            float a0 = sT2[j * NG + g0];
            float a1 = sT2[j * NG + g0 + 1];
            if (f0 == 0) { c1a += a0; c1b += a1; }
            const float4* xr = (const float4*)(sX + j * NF + f0);
#pragma unroll
            for (int q = 0; q < 4; q++) {
                float4 xv = xr[q];
                ra[0][q * 4 + 0] += a0 * xv.x; ra[0][q * 4 + 1] += a0 * xv.y;
                ra[0][q * 4 + 2] += a0 * xv.z; ra[0][q * 4 + 3] += a0 * xv.w;
                ra[1][q * 4 + 0] += a1 * xv.x; ra[1][q * 4 + 1] += a1 * xv.y;
                ra[1][q * 4 + 2] += a1 * xv.z; ra[1][q * 4 + 3] += a1 * xv.w;
            }
        }
    }
#pragma unroll
    for (int a = 0; a < 2; a++)
#pragma unroll
        for (int b = 0; b < 16; b++)
            atomicAdd(&d_G[(g0 + a) * NF + f0 + b], ra[a][b]);
    if (f0 == 0) {
        atomicAdd(&d_c1[g0], c1a);
        atomicAdd(&d_c1[g0 + 1], c1b);
    }
}

// M1 = G @ W1   [64 x 128]
__global__ void k_M1(const float* __restrict__ W1) {
    __shared__ float gr[NF];
    int g = blockIdx.x, f = threadIdx.x;
    gr[f] = d_G[g * NF + f];
    __syncthreads();
    float acc = 0.0f;
#pragma unroll 8
    for (int k = 0; k < NF; k++) acc += gr[k] * W1[k * NH + f];
    d_M1[g * NH + f] = acc;
}

// pooled = M1 @ W2 + c1*(b1@W2) + s*b2 ; log_softmax
__global__ void k_final(const float* __restrict__ W2, const float* __restrict__ b1,
                        const float* __restrict__ b2, float* __restrict__ out) {
    __shared__ float sW2[NH * NC];
    __shared__ float sbW2[NC];
    int t = threadIdx.x;   // 64 threads, one per graph
    for (int j = t; j < NH * NC; j += 64) sW2[j] = W2[j];
    __syncthreads();
    if (t < NC) {
        float a = 0.0f;
        for (int f = 0; f < NH; f++) a += b1[f] * sW2[f * NC + t];
        sbW2[t] = a;
    }
    __syncthreads();
    int g = t;
    float p[NC];
    float c1 = d_c1[g], s = d_s[g];
#pragma unroll
    for (int c = 0; c < NC; c++) p[c] = c1 * sbW2[c] + s * b2[c];
    for (int f = 0; f < NH; f++) {
        float m = d_M1[g * NH + f];
#pragma unroll
        for (int c = 0; c < NC; c++) p[c] += m * sW2[f * NC + c];
    }
    float mx = p[0];
#pragma unroll
    for (int c = 1; c < NC; c++) mx = fmaxf(mx, p[c]);
    float se = 0.0f;
#pragma unroll
    for (int c = 0; c < NC; c++) se += expf(p[c] - mx);
    float l = logf(se);
#pragma unroll
    for (int c = 0; c < NC; c++) out[g * NC + c] = p[c] - mx - l;
}

// ---------------- launch ----------------
extern "C" void kernel_launch(void* const* d_in, const int* in_sizes, int n_in,
                              void* d_out, int out_size) {
    const float* x = (const float*)d_in[0];
    const void*  ei = d_in[1];
    const void*  batch = d_in[2];
    // num_graphs may or may not be present as a scalar input
    int w = (in_sizes[3] == 1) ? 4 : 3;
    const float* W1 = (const float*)d_in[w + 0];
    const float* b1 = (const float*)d_in[w + 1];
    const float* W2 = (const float*)d_in[w + 2];
    const float* b2 = (const float*)d_in[w + 3];
    float* out = (float*)d_out;

    void* p;
    cudaGetSymbolAddress(&p, d_deg);  cudaMemsetAsync(p, 0, sizeof(float) * N_NODES);
    cudaGetSymbolAddress(&p, d_cnt);  cudaMemsetAsync(p, 0, sizeof(float) * NG);
    cudaGetSymbolAddress(&p, d_t1);   cudaMemsetAsync(p, 0, sizeof(float) * N_NODES * NG);
    cudaGetSymbolAddress(&p, d_t2);   cudaMemsetAsync(p, 0, sizeof(float) * N_NODES * NG);
    cudaGetSymbolAddress(&p, d_s);    cudaMemsetAsync(p, 0, sizeof(float) * NG);
    cudaGetSymbolAddress(&p, d_c1);   cudaMemsetAsync(p, 0, sizeof(float) * NG);
    cudaGetSymbolAddress(&p, d_G);    cudaMemsetAsync(p, 0, sizeof(float) * NG * NF);

    k_detect<<<1, 32>>>(ei);

    int itemsEN = N_EDGES + N_NODES;
    k_deg<<<(itemsEN + 255) / 256, 256>>>(ei, batch);
    k_dis<<<(N_NODES + 255) / 256, 256>>>();
    k_t1<<<(itemsEN + 255) / 256, 256>>>(ei, batch);

    long long t2threads = (long long)itemsEN * 8;
    k_t2<<<(int)((t2threads + 255) / 256), 256>>>(ei);

    k_s<<<512, 256>>>();
    k_G<<<592, 256>>>(x);
    k_M1<<<NG, NF>>>(W1);
    k_final<<<1, NG>>>(W2, b1, b2, out);
}

// round 5
// speedup vs baseline: 2.4257x; 2.4257x over previous
#include <cuda_runtime.h>
#include <cstdint>

#define N_NODES 100000
#define N_EDGES 1600000
#define NF 128
#define NC 10
#define NW 12      // padded propagation width (10 classes + 2 zero pad, 48B rows)
#define NG 64

// ---------------- scratch (static __device__, no allocation) ----------------
__device__ __align__(16) float d_deg[N_NODES];       // edge-only degree
__device__ __align__(16) float d_dis[N_NODES];       // rsqrt(deg+1)
__device__ __align__(16) int2  d_rc[N_EDGES];
__device__ __align__(16) float d_nv[N_EDGES];
__device__ __align__(16) float d_u [N_NODES * NW];   // x @ Wc   (4.8 MB)
__device__ __align__(16) float d_h1[N_NODES * NW];   // layer-1 result (+bias folded)
__device__ __align__(16) float d_h2[N_NODES * NW];   // layer-2 edge part
__device__ __align__(16) float d_a1[N_NODES];        // A^ 1
__device__ __align__(16) float d_Wc[NF * NW];        // W1 @ W2, padded
__device__ __align__(16) float d_bw[NW];             // b1 @ W2, padded
__device__ float d_pool[NG * NC];
__device__ float d_gcnt[NG];
__device__ int   d_is64;

// ---------------- helpers ----------------
__device__ __forceinline__ int read_idx(const void* p, long long i, int is64) {
    return is64 ? (int)((const long long*)p)[i] : ((const int*)p)[i];
}
__device__ __forceinline__ void red4(float* addr, float x, float y, float z, float w) {
    asm volatile("red.global.add.v4.f32 [%0], {%1,%2,%3,%4};"
                 :: "l"(addr), "f"(x), "f"(y), "f"(z), "f"(w) : "memory");
}

// Detect int64 vs int32 indices (high words of small nonneg int64 are zero)
__global__ void k_detect(const void* ei) {
    const int* p = (const int*)ei;
    unsigned ok = __ballot_sync(0xFFFFFFFFu, p[2 * threadIdx.x + 1] == 0);
    if (threadIdx.x == 0) d_is64 = (ok == 0xFFFFFFFFu) ? 1 : 0;
}

// deg[col] += 1 per edge (self-loop folded into k_dis as +1)
__global__ void __launch_bounds__(256) k_deg(const void* ei) {
    int i = blockIdx.x * blockDim.x + threadIdx.x;
    if (i >= N_EDGES) return;
    int c = read_idx(ei, (long long)N_EDGES + i, d_is64);
    atomicAdd(&d_deg[c], 1.0f);
}

__global__ void __launch_bounds__(256) k_dis() {
    int i = blockIdx.x * blockDim.x + threadIdx.x;
    if (i >= N_NODES) return;
    d_dis[i] = rsqrtf(d_deg[i] + 1.0f);   // deg incl. self-loop is always >= 1
}

// pack edges: rc[e] = {row, col}, nv[e] = dis[row]*dis[col]
__global__ void __launch_bounds__(256) k_prep(const void* ei) {
    int e = blockIdx.x * blockDim.x + threadIdx.x;
    if (e >= N_EDGES) return;
    int is64 = d_is64;
    int r = read_idx(ei, e, is64);
    int c = read_idx(ei, (long long)N_EDGES + e, is64);
    d_rc[e] = make_int2(r, c);
    d_nv[e] = d_dis[r] * d_dis[c];
}

// Wc = W1 @ W2 (128x10, padded to 12), bw = b1 @ W2
__global__ void __launch_bounds__(128) k_wc(const float* __restrict__ W1,
                                            const float* __restrict__ W2,
                                            const float* __restrict__ b1) {
    __shared__ float sW2[NF * NC];
    int t = threadIdx.x;   // 128 threads, t = input-feature row
    for (int j = t; j < NF * NC; j += NF) sW2[j] = W2[j];
    __syncthreads();
    float acc[NC];
#pragma unroll
    for (int c = 0; c < NC; c++) acc[c] = 0.0f;
    for (int f = 0; f < NF; f++) {
        float w = W1[t * NF + f];
#pragma unroll
        for (int c = 0; c < NC; c++) acc[c] += w * sW2[f * NC + c];
    }
#pragma unroll
    for (int c = 0; c < NC; c++) d_Wc[t * NW + c] = acc[c];
    d_Wc[t * NW + 10] = 0.0f; d_Wc[t * NW + 11] = 0.0f;
    if (t < NC) {
        float a = 0.0f;
        for (int f = 0; f < NF; f++) a += b1[f] * sW2[f * NC + t];
        d_bw[t] = a;
    }
    if (t == 0) { d_bw[10] = 0.0f; d_bw[11] = 0.0f; }
}

// u = x @ Wc  (thread per node, Wc broadcast from shared)
__global__ void __launch_bounds__(256) k_u(const float* __restrict__ x) {
    __shared__ float4 sWc[NF * 3];
    int t = threadIdx.x;
    for (int j = t; j < NF * 3; j += 256) sWc[j] = ((const float4*)d_Wc)[j];
    __syncthreads();
    int n = blockIdx.x * 256 + t;
    if (n >= N_NODES) return;
    float4 a0 = make_float4(0,0,0,0), a1 = a0, a2 = a0;
    const float4* xr = (const float4*)(x + (size_t)n * NF);
#pragma unroll 4
    for (int k4 = 0; k4 < NF / 4; k4++) {
        float4 xv = __ldg(&xr[k4]);
#pragma unroll
        for (int kk = 0; kk < 4; kk++) {
            float s = (kk == 0) ? xv.x : (kk == 1) ? xv.y : (kk == 2) ? xv.z : xv.w;
            int k = k4 * 4 + kk;
            float4 w0 = sWc[k * 3 + 0], w1 = sWc[k * 3 + 1], w2 = sWc[k * 3 + 2];
            a0.x += s * w0.x; a0.y += s * w0.y; a0.z += s * w0.z; a0.w += s * w0.w;
            a1.x += s * w1.x; a1.y += s * w1.y; a1.z += s * w1.z; a1.w += s * w1.w;
            a2.x += s * w2.x; a2.y += s * w2.y; a2.z += s * w2.z; a2.w += s * w2.w;
        }
    }
    float4* ur = (float4*)(d_u + (size_t)n * NW);
    ur[0] = a0; ur[1] = a1; ur[2] = a2;
}

// pass 1 (edges only): h1[col] += nv*u[row]; a1[col] += nv
__global__ void __launch_bounds__(256) k_pass1() {
    int e = blockIdx.x * blockDim.x + threadIdx.x;
    if (e >= N_EDGES) return;
    int2 rc = d_rc[e];
    float nv = d_nv[e];
    const float4* s = (const float4*)(d_u + (size_t)rc.x * NW);
    float4 v0 = s[0], v1 = s[1], v2 = s[2];
    float* d = d_h1 + (size_t)rc.y * NW;
    red4(d,     v0.x * nv, v0.y * nv, v0.z * nv, v0.w * nv);
    red4(d + 4, v1.x * nv, v1.y * nv, v1.z * nv, v1.w * nv);
    red4(d + 8, v2.x * nv, v2.y * nv, v2.z * nv, v2.w * nv);
    atomicAdd(&d_a1[rc.y], nv);
}

// post pass 1 (elementwise, non-atomic): self-loop + b1W2 bias
// a1 <- a1 + dis^2 ; h1 <- h1 + dis^2*u + a1_final*bw
__global__ void __launch_bounds__(256) k_post1() {
    int n = blockIdx.x * blockDim.x + threadIdx.x;
    if (n >= N_NODES) return;
    float ds = d_dis[n];
    float s2 = ds * ds;
    float a = d_a1[n] + s2;
    d_a1[n] = a;
    float4* h = (float4*)(d_h1 + (size_t)n * NW);
    const float4* u = (const float4*)(d_u + (size_t)n * NW);
    const float4* bw = (const float4*)d_bw;
#pragma unroll
    for (int q = 0; q < 3; q++) {
        float4 v = h[q], uv = u[q], bv = bw[q];
        v.x += s2 * uv.x + a * bv.x;
        v.y += s2 * uv.y + a * bv.y;
        v.z += s2 * uv.z + a * bv.z;
        v.w += s2 * uv.w + a * bv.w;
        h[q] = v;
    }
}

// pass 2 (edges only): h2[col] += nv*h1[row]
__global__ void __launch_bounds__(256) k_pass2() {
    int e = blockIdx.x * blockDim.x + threadIdx.x;
    if (e >= N_EDGES) return;
    int2 rc = d_rc[e];
    float nv = d_nv[e];
    const float4* s = (const float4*)(d_h1 + (size_t)rc.x * NW);
    float4 v0 = s[0], v1 = s[1], v2 = s[2];
    float* d = d_h2 + (size_t)rc.y * NW;
    red4(d,     v0.x * nv, v0.y * nv, v0.z * nv, v0.w * nv);
    red4(d + 4, v1.x * nv, v1.y * nv, v1.z * nv, v1.w * nv);
    red4(d + 8, v2.x * nv, v2.y * nv, v2.z * nv, v2.w * nv);
}

// pool: node value = h2 + dis^2*h1 (self-loop) + a1*b2 ; mean-pool prep
__global__ void __launch_bounds__(256) k_pool(const void* batch, const float* __restrict__ b2) {
    __shared__ float sp[NG * NC];
    __shared__ float sc[NG];
    __shared__ float sb2[NC];
    int t = threadIdx.x;
    for (int j = t; j < NG * NC; j += 256) sp[j] = 0.0f;
    if (t < NG) sc[t] = 0.0f;
    if (t < NC) sb2[t] = b2[t];
    __syncthreads();
    int n = blockIdx.x * 256 + t;
    if (n < N_NODES) {
        int g = read_idx(batch, n, d_is64);
        float ds = d_dis[n];
        float s2 = ds * ds;
        float a = d_a1[n];
        const float* h2 = d_h2 + (size_t)n * NW;
        const float* h1 = d_h1 + (size_t)n * NW;
#pragma unroll
        for (int c = 0; c < NC; c++)
            atomicAdd(&sp[g * NC + c], h2[c] + s2 * h1[c] + a * sb2[c]);
        atomicAdd(&sc[g], 1.0f);
    }
    __syncthreads();
    for (int j = t; j < NG * NC; j += 256)
        if (sp[j] != 0.0f) atomicAdd(&d_pool[j], sp[j]);
    if (t < NG && sc[t] != 0.0f) atomicAdd(&d_gcnt[t], sc[t]);
}

// divide by counts, log_softmax, write out
__global__ void __launch_bounds__(64) k_final(float* __restrict__ out) {
    int g = threadIdx.x;   // 64 threads
    float inv = 1.0f / fmaxf(d_gcnt[g], 1.0f);
    float p[NC];
#pragma unroll
    for (int c = 0; c < NC; c++) p[c] = d_pool[g * NC + c] * inv;
    float mx = p[0];
#pragma unroll
    for (int c = 1; c < NC; c++) mx = fmaxf(mx, p[c]);
    float se = 0.0f;
#pragma unroll
    for (int c = 0; c < NC; c++) se += expf(p[c] - mx);
    float l = logf(se);
#pragma unroll
    for (int c = 0; c < NC; c++) out[g * NC + c] = p[c] - mx - l;
}

// ---------------- launch ----------------
extern "C" void kernel_launch(void* const* d_in, const int* in_sizes, int n_in,
                              void* d_out, int out_size) {
    const float* x = (const float*)d_in[0];
    const void*  ei = d_in[1];
    const void*  batch = d_in[2];
    int w = (in_sizes[3] == 1) ? 4 : 3;   // num_graphs scalar may be present
    const float* W1 = (const float*)d_in[w + 0];
    const float* b1 = (const float*)d_in[w + 1];
    const float* W2 = (const float*)d_in[w + 2];
    const float* b2 = (const float*)d_in[w + 3];
    float* out = (float*)d_out;

    void* p;
    cudaGetSymbolAddress(&p, d_deg);  cudaMemsetAsync(p, 0, sizeof(float) * N_NODES);
    cudaGetSymbolAddress(&p, d_a1);   cudaMemsetAsync(p, 0, sizeof(float) * N_NODES);
    cudaGetSymbolAddress(&p, d_h1);   cudaMemsetAsync(p, 0, sizeof(float) * N_NODES * NW);
    cudaGetSymbolAddress(&p, d_h2);   cudaMemsetAsync(p, 0, sizeof(float) * N_NODES * NW);
    cudaGetSymbolAddress(&p, d_pool); cudaMemsetAsync(p, 0, sizeof(float) * NG * NC);
    cudaGetSymbolAddress(&p, d_gcnt); cudaMemsetAsync(p, 0, sizeof(float) * NG);

    k_detect<<<1, 32>>>(ei);

    k_deg <<<(N_EDGES + 255) / 256, 256>>>(ei);
    k_dis <<<(N_NODES + 255) / 256, 256>>>();
    k_prep<<<(N_EDGES + 255) / 256, 256>>>(ei);
    k_wc  <<<1, NF>>>(W1, W2, b1);
    k_u   <<<(N_NODES + 255) / 256, 256>>>(x);

    k_pass1<<<(N_EDGES + 255) / 256, 256>>>();
    k_post1<<<(N_NODES + 255) / 256, 256>>>();
    k_pass2<<<(N_EDGES + 255) / 256, 256>>>();

    k_pool<<<(N_NODES + 255) / 256, 256>>>(batch, b2);
    k_final<<<1, NG>>>(out);
}

// round 6
// speedup vs baseline: 2.4948x; 1.0285x over previous
#include <cuda_runtime.h>
#include <cstdint>

#define N_NODES 100000
#define N_EDGES 1600000
#define NF 128
#define NC 10
#define NW 12      // padded propagation width (10 classes + a1 lane + pad, 48B rows)
#define NG 64

#define PACK_BLOCKS ((N_EDGES + 255) / 256)   // 6250
#define U_BLOCKS    ((N_NODES + 255) / 256)   // 391

// ---------------- scratch (static __device__, no allocation) ----------------
__device__ __align__(16) float d_deg[N_NODES];       // edge-only degree (self-loop = +1 implicit)
__device__ __align__(16) int2  d_rc[N_EDGES];
__device__ __align__(16) float d_nv[N_EDGES];        // written by pass1, read by pass2
__device__ __align__(16) float d_u [N_NODES * NW];   // x @ Wc
__device__ __align__(16) float d_h1[N_NODES * NW];   // layer-1 (lane 10 = a1 edge part)
__device__ __align__(16) float d_h2[N_NODES * NW];   // layer-2 edge part
__device__ __align__(16) float d_a1[N_NODES];        // finalized A^ 1
__device__ __align__(16) float d_Wc[NF * NW];        // W1 @ W2, padded (lanes 10,11 = 0)
__device__ __align__(16) float d_bw[NW];             // b1 @ W2, padded
__device__ float d_pool[NG * NC];
__device__ float d_gcnt[NG];
__device__ int   d_is64;

// ---------------- helpers ----------------
__device__ __forceinline__ int read_idx(const void* p, long long i, int is64) {
    return is64 ? (int)((const long long*)p)[i] : ((const int*)p)[i];
}
__device__ __forceinline__ void red4(float* addr, float x, float y, float z, float w) {
    asm volatile("red.global.add.v4.f32 [%0], {%1,%2,%3,%4};"
                 :: "l"(addr), "f"(x), "f"(y), "f"(z), "f"(w) : "memory");
}

// Detect int64 vs int32 indices (high words of small nonneg int64 are zero)
__global__ void k_detect(const void* ei) {
    const int* p = (const int*)ei;
    unsigned ok = __ballot_sync(0xFFFFFFFFu, p[2 * threadIdx.x + 1] == 0);
    if (threadIdx.x == 0) d_is64 = (ok == 0xFFFFFFFFu) ? 1 : 0;
}

// Wc = W1 @ W2 (128x10, padded to 12), bw = b1 @ W2
__global__ void __launch_bounds__(128) k_wc(const float* __restrict__ W1,
                                            const float* __restrict__ W2,
                                            const float* __restrict__ b1) {
    __shared__ float sW2[NF * NC];
    int t = threadIdx.x;   // t = input-feature row
    for (int j = t; j < NF * NC; j += NF) sW2[j] = W2[j];
    __syncthreads();
    float acc[NC];
#pragma unroll
    for (int c = 0; c < NC; c++) acc[c] = 0.0f;
    for (int f = 0; f < NF; f++) {
        float w = W1[t * NF + f];
#pragma unroll
        for (int c = 0; c < NC; c++) acc[c] += w * sW2[f * NC + c];
    }
#pragma unroll
    for (int c = 0; c < NC; c++) d_Wc[t * NW + c] = acc[c];
    d_Wc[t * NW + 10] = 0.0f; d_Wc[t * NW + 11] = 0.0f;
    if (t < NC) {
        float a = 0.0f;
        for (int f = 0; f < NF; f++) a += b1[f] * sW2[f * NC + t];
        d_bw[t] = a;
    }
    if (t == 0) { d_bw[10] = 0.0f; d_bw[11] = 0.0f; }
}

// Fat kernel: blocks [0, PACK_BLOCKS) pack edges + degree atomics;
//             blocks [PACK_BLOCKS, PACK_BLOCKS+U_BLOCKS) compute u = x @ Wc.
// The two halves are independent; fusing them overlaps DRAM-bound u with
// L2-atomic-bound pack.
__global__ void __launch_bounds__(256) k_fat(const void* ei, const float* __restrict__ x) {
    if (blockIdx.x < PACK_BLOCKS) {
        int e = blockIdx.x * 256 + threadIdx.x;
        if (e >= N_EDGES) return;
        int is64 = d_is64;
        int r = read_idx(ei, e, is64);
        int c = read_idx(ei, (long long)N_EDGES + e, is64);
        d_rc[e] = make_int2(r, c);
        atomicAdd(&d_deg[c], 1.0f);
    } else {
        __shared__ float4 sWc[NF * 3];
        int t = threadIdx.x;
        for (int j = t; j < NF * 3; j += 256) sWc[j] = ((const float4*)d_Wc)[j];
        __syncthreads();
        int n = (blockIdx.x - PACK_BLOCKS) * 256 + t;
        if (n >= N_NODES) return;
        float4 a0 = make_float4(0,0,0,0), a1 = a0, a2 = a0;
        const float4* xr = (const float4*)(x + (size_t)n * NF);
#pragma unroll 4
        for (int k4 = 0; k4 < NF / 4; k4++) {
            float4 xv = __ldg(&xr[k4]);
#pragma unroll
            for (int kk = 0; kk < 4; kk++) {
                float s = (kk == 0) ? xv.x : (kk == 1) ? xv.y : (kk == 2) ? xv.z : xv.w;
                int k = k4 * 4 + kk;
                float4 w0 = sWc[k * 3 + 0], w1 = sWc[k * 3 + 1], w2 = sWc[k * 3 + 2];
                a0.x += s * w0.x; a0.y += s * w0.y; a0.z += s * w0.z; a0.w += s * w0.w;
                a1.x += s * w1.x; a1.y += s * w1.y; a1.z += s * w1.z; a1.w += s * w1.w;
                a2.x += s * w2.x; a2.y += s * w2.y; a2.z += s * w2.z; a2.w += s * w2.w;
            }
        }
        float4* ur = (float4*)(d_u + (size_t)n * NW);
        ur[0] = a0; ur[1] = a1; ur[2] = a2;
    }
}

// pass 1: nv = rsqrt((deg_r+1)(deg_c+1)); store nv; h1[col] += nv*u[row];
// a1 edge-part accumulates in lane 10 (u lane 10 is 0).
__global__ void __launch_bounds__(256) k_pass1() {
    int e = blockIdx.x * blockDim.x + threadIdx.x;
    if (e >= N_EDGES) return;
    int2 rc = d_rc[e];
    float dr = d_deg[rc.x], dc = d_deg[rc.y];
    float nv = rsqrtf((dr + 1.0f) * (dc + 1.0f));
    d_nv[e] = nv;
    const float4* s = (const float4*)(d_u + (size_t)rc.x * NW);
    float4 v0 = s[0], v1 = s[1], v2 = s[2];
    float* d = d_h1 + (size_t)rc.y * NW;
    red4(d,     v0.x * nv, v0.y * nv, v0.z * nv, v0.w * nv);
    red4(d + 4, v1.x * nv, v1.y * nv, nv,        0.0f);       // lane 10 = a1
    red4(d + 8, v2.x * nv, v2.y * nv, 0.0f,      0.0f);
}
// NOTE on lanes: u row layout is [c0..c9, 0, 0]; classes 0-9 occupy lanes 0-9.
// v1 covers lanes 4-7, v2 lanes 8-11?? -> careful: s[0]=lanes0-3, s[1]=lanes4-7,
// s[2]=lanes8-11 (c8,c9,0,0). a1 must go to lane 10 = v2.z position.

// pass 1 corrected version is above? No — fix: a1 belongs in the THIRD red, lane 10.
// (kept as a separate corrected kernel to avoid confusion)
__global__ void __launch_bounds__(256) k_pass1_fix() {
    int e = blockIdx.x * blockDim.x + threadIdx.x;
    if (e >= N_EDGES) return;
    int2 rc = d_rc[e];
    float dr = d_deg[rc.x], dc = d_deg[rc.y];
    float nv = rsqrtf((dr + 1.0f) * (dc + 1.0f));
    d_nv[e] = nv;
    const float4* s = (const float4*)(d_u + (size_t)rc.x * NW);
    float4 v0 = s[0], v1 = s[1], v2 = s[2];
    float* d = d_h1 + (size_t)rc.y * NW;
    red4(d,     v0.x * nv, v0.y * nv, v0.z * nv, v0.w * nv);
    red4(d + 4, v1.x * nv, v1.y * nv, v1.z * nv, v1.w * nv);
    red4(d + 8, v2.x * nv, v2.y * nv, nv,        0.0f);       // lane 10 = a1
}

// post pass 1: a1 = h1[lane10] + s2 ; h1 += s2*u + a1*bw ; store d_a1
__global__ void __launch_bounds__(256) k_post1() {
    int n = blockIdx.x * blockDim.x + threadIdx.x;
    if (n >= N_NODES) return;
    float s2 = 1.0f / (d_deg[n] + 1.0f);     // dis^2
    float4* h = (float4*)(d_h1 + (size_t)n * NW);
    float4 h0 = h[0], h1v = h[1], h2v = h[2];
    float a = h2v.z + s2;                     // lane 10 + self-loop
    d_a1[n] = a;
    const float4* u = (const float4*)(d_u + (size_t)n * NW);
    const float4* bw = (const float4*)d_bw;
    float4 u0 = u[0], u1 = u[1], u2 = u[2];
    float4 b0 = bw[0], b1v = bw[1], b2v = bw[2];
    h0.x += s2 * u0.x + a * b0.x;  h0.y += s2 * u0.y + a * b0.y;
    h0.z += s2 * u0.z + a * b0.z;  h0.w += s2 * u0.w + a * b0.w;
    h1v.x += s2 * u1.x + a * b1v.x; h1v.y += s2 * u1.y + a * b1v.y;
    h1v.z += s2 * u1.z + a * b1v.z; h1v.w += s2 * u1.w + a * b1v.w;
    h2v.x += s2 * u2.x + a * b2v.x; h2v.y += s2 * u2.y + a * b2v.y;
    h2v.z = 0.0f; h2v.w = 0.0f;               // clean pad lanes for pass2
    h[0] = h0; h[1] = h1v; h[2] = h2v;
}

// pass 2: h2[col] += nv*h1[row]
__global__ void __launch_bounds__(256) k_pass2() {
    int e = blockIdx.x * blockDim.x + threadIdx.x;
    if (e >= N_EDGES) return;
    int2 rc = d_rc[e];
    float nv = d_nv[e];
    const float4* s = (const float4*)(d_h1 + (size_t)rc.x * NW);
    float4 v0 = s[0], v1 = s[1], v2 = s[2];
    float* d = d_h2 + (size_t)rc.y * NW;
    red4(d,     v0.x * nv, v0.y * nv, v0.z * nv, v0.w * nv);
    red4(d + 4, v1.x * nv, v1.y * nv, v1.z * nv, v1.w * nv);
    red4(d + 8, v2.x * nv, v2.y * nv, 0.0f,      0.0f);
}

// pool: node value = h2 + s2*h1 (self-loop) + a1*b2 ; mean-pool accumulate
__global__ void __launch_bounds__(256) k_pool(const void* batch, const float* __restrict__ b2) {
    __shared__ float sp[NG * NC];
    __shared__ float sc[NG];
    __shared__ float sb2[NC];
    int t = threadIdx.x;
    for (int j = t; j < NG * NC; j += 256) sp[j] = 0.0f;
    if (t < NG) sc[t] = 0.0f;
    if (t < NC) sb2[t] = b2[t];
    __syncthreads();
    int n = blockIdx.x * 256 + t;
    if (n < N_NODES) {
        int g = read_idx(batch, n, d_is64);
        float s2 = 1.0f / (d_deg[n] + 1.0f);
        float a = d_a1[n];
        const float* h2 = d_h2 + (size_t)n * NW;
        const float* h1 = d_h1 + (size_t)n * NW;
#pragma unroll
        for (int c = 0; c < NC; c++)
            atomicAdd(&sp[g * NC + c], h2[c] + s2 * h1[c] + a * sb2[c]);
        atomicAdd(&sc[g], 1.0f);
    }
    __syncthreads();
    for (int j = t; j < NG * NC; j += 256)
        if (sp[j] != 0.0f) atomicAdd(&d_pool[j], sp[j]);
    if (t < NG && sc[t] != 0.0f) atomicAdd(&d_gcnt[t], sc[t]);
}

// divide by counts, log_softmax, write out
__global__ void __launch_bounds__(64) k_final(float* __restrict__ out) {
    int g = threadIdx.x;
    float inv = 1.0f / fmaxf(d_gcnt[g], 1.0f);
    float p[NC];
#pragma unroll
    for (int c = 0; c < NC; c++) p[c] = d_pool[g * NC + c] * inv;
    float mx = p[0];
#pragma unroll
    for (int c = 1; c < NC; c++) mx = fmaxf(mx, p[c]);
    float se = 0.0f;
#pragma unroll
    for (int c = 0; c < NC; c++) se += expf(p[c] - mx);
    float l = logf(se);
#pragma unroll
    for (int c = 0; c < NC; c++) out[g * NC + c] = p[c] - mx - l;
}

// ---------------- launch ----------------
extern "C" void kernel_launch(void* const* d_in, const int* in_sizes, int n_in,
                              void* d_out, int out_size) {
    const float* x = (const float*)d_in[0];
    const void*  ei = d_in[1];
    const void*  batch = d_in[2];
    int w = (in_sizes[3] == 1) ? 4 : 3;   // num_graphs scalar may be present
    const float* W1 = (const float*)d_in[w + 0];
    const float* b1 = (const float*)d_in[w + 1];
    const float* W2 = (const float*)d_in[w + 2];
    const float* b2 = (const float*)d_in[w + 3];
    float* out = (float*)d_out;

    void* p;
    cudaGetSymbolAddress(&p, d_deg);  cudaMemsetAsync(p, 0, sizeof(float) * N_NODES);
    cudaGetSymbolAddress(&p, d_h1);   cudaMemsetAsync(p, 0, sizeof(float) * N_NODES * NW);
    cudaGetSymbolAddress(&p, d_h2);   cudaMemsetAsync(p, 0, sizeof(float) * N_NODES * NW);
    cudaGetSymbolAddress(&p, d_pool); cudaMemsetAsync(p, 0, sizeof(float) * NG * NC);
    cudaGetSymbolAddress(&p, d_gcnt); cudaMemsetAsync(p, 0, sizeof(float) * NG);

    k_detect<<<1, 32>>>(ei);
    k_wc  <<<1, NF>>>(W1, W2, b1);
    k_fat <<<PACK_BLOCKS + U_BLOCKS, 256>>>(ei, x);

    k_pass1_fix<<<(N_EDGES + 255) / 256, 256>>>();
    k_post1    <<<(N_NODES + 255) / 256, 256>>>();
    k_pass2    <<<(N_EDGES + 255) / 256, 256>>>();

    k_pool<<<(N_NODES + 255) / 256, 256>>>(batch, b2);
    k_final<<<1, NG>>>(out);
}

// round 8
// speedup vs baseline: 2.7399x; 1.0982x over previous
#include <cuda_runtime.h>
#include <cuda_fp16.h>
#include <cstdint>

#define N_NODES 100000
#define N_EDGES 1600000
#define NF 128
#define NC 10
#define NG 64
#define RW 6   // half2 lanes per row (10 classes packed in 5 + aux lane)

#define PACK_BLOCKS ((N_EDGES + 255) / 256)   // 6250
#define U_BLOCKS    ((N_NODES + 255) / 256)   // 391

// ---------------- scratch ----------------
__device__ __align__(16) float    d_deg[N_NODES];        // edge-only degree
__device__ __align__(16) int2     d_rc[N_EDGES];
__device__ __align__(16) float    d_u [N_NODES * 12];    // x @ Wc (f32, 12-wide)
__device__ __align__(16) unsigned d_uf[N_NODES * RW];    // dis*u fp16x2; lane5 = (dis, 0)
__device__ __align__(16) unsigned d_hf[2 * N_NODES * RW]; // [h1f | h2f]
__device__ __align__(16) float    d_a1[N_NODES];
__device__ __align__(16) float    d_Wc[NF * 12];
__device__ __align__(16) float    d_bw[12];
__device__ float d_pool[NG * NC];
__device__ float d_gcnt[NG];
__device__ int   d_is64;

#define H1F d_hf
#define H2F (d_hf + N_NODES * RW)

// ---------------- helpers ----------------
__device__ __forceinline__ int read_idx(const void* p, long long i, int is64) {
    return is64 ? (int)((const long long*)p)[i] : ((const int*)p)[i];
}
__device__ __forceinline__ void redv2h(unsigned* addr, unsigned a, unsigned b) {
    asm volatile("red.global.add.noftz.v2.f16x2 [%0], {%1,%2};"
                 :: "l"(addr), "r"(a), "r"(b) : "memory");
}
__device__ __forceinline__ void redh(unsigned* addr, unsigned a) {
    asm volatile("red.global.add.noftz.f16x2 [%0], %1;"
                 :: "l"(addr), "r"(a) : "memory");
}
__device__ __forceinline__ unsigned pack2(float lo, float hi) {
    __half2 h = __floats2half2_rn(lo, hi);
    return *reinterpret_cast<unsigned*>(&h);
}
__device__ __forceinline__ float2 unpack2(unsigned u) {
    __half2 h = *reinterpret_cast<__half2*>(&u);
    return make_float2(__low2float(h), __high2float(h));
}

// detect int64 indices (block 0) + Wc = W1@W2, bw = b1@W2 (block 1)
__global__ void __launch_bounds__(128) k_init(const void* ei,
                                              const float* __restrict__ W1,
                                              const float* __restrict__ W2,
                                              const float* __restrict__ b1) {
    if (blockIdx.x == 0) {
        if (threadIdx.x < 32) {
            const int* p = (const int*)ei;
            unsigned ok = __ballot_sync(0xFFFFFFFFu, p[2 * threadIdx.x + 1] == 0);
            if (threadIdx.x == 0) d_is64 = (ok == 0xFFFFFFFFu) ? 1 : 0;
        }
        return;
    }
    __shared__ float sW2[NF * NC];
    int t = threadIdx.x;                       // t = input-feature row
    for (int j = t; j < NF * NC; j += NF) sW2[j] = W2[j];
    __syncthreads();
    float acc[NC];
#pragma unroll
    for (int c = 0; c < NC; c++) acc[c] = 0.0f;
    for (int f = 0; f < NF; f++) {
        float w = W1[t * NF + f];
#pragma unroll
        for (int c = 0; c < NC; c++) acc[c] += w * sW2[f * NC + c];
    }
#pragma unroll
    for (int c = 0; c < NC; c++) d_Wc[t * 12 + c] = acc[c];
    d_Wc[t * 12 + 10] = 0.0f; d_Wc[t * 12 + 11] = 0.0f;
    if (t < NC) {
        float a = 0.0f;
        for (int f = 0; f < NF; f++) a += b1[f] * sW2[f * NC + t];
        d_bw[t] = a;
    }
    if (t == 0) { d_bw[10] = 0.0f; d_bw[11] = 0.0f; }
}

// Fat: blocks [0,PACK) pack rc + degree atomics; trailing blocks u = x @ Wc (f32)
__global__ void __launch_bounds__(256) k_fat(const void* ei, const float* __restrict__ x) {
    if (blockIdx.x < PACK_BLOCKS) {
        int e = blockIdx.x * 256 + threadIdx.x;
        if (e >= N_EDGES) return;
        int is64 = d_is64;
        int r = read_idx(ei, e, is64);
        int c = read_idx(ei, (long long)N_EDGES + e, is64);
        d_rc[e] = make_int2(r, c);
        atomicAdd(&d_deg[c], 1.0f);
    } else {
        __shared__ float4 sWc[NF * 3];
        int t = threadIdx.x;
        for (int j = t; j < NF * 3; j += 256) sWc[j] = ((const float4*)d_Wc)[j];
        __syncthreads();
        int n = (blockIdx.x - PACK_BLOCKS) * 256 + t;
        if (n >= N_NODES) return;
        float4 a0 = make_float4(0,0,0,0), a1 = a0, a2 = a0;
        const float4* xr = (const float4*)(x + (size_t)n * NF);
#pragma unroll 4
        for (int k4 = 0; k4 < NF / 4; k4++) {
            float4 xv = __ldg(&xr[k4]);
#pragma unroll
            for (int kk = 0; kk < 4; kk++) {
                float s = (kk == 0) ? xv.x : (kk == 1) ? xv.y : (kk == 2) ? xv.z : xv.w;
                int k = k4 * 4 + kk;
                float4 w0 = sWc[k * 3 + 0], w1 = sWc[k * 3 + 1], w2 = sWc[k * 3 + 2];
                a0.x += s * w0.x; a0.y += s * w0.y; a0.z += s * w0.z; a0.w += s * w0.w;
                a1.x += s * w1.x; a1.y += s * w1.y; a1.z += s * w1.z; a1.w += s * w1.w;
                a2.x += s * w2.x; a2.y += s * w2.y; a2.z += s * w2.z; a2.w += s * w2.w;
            }
        }
        float4* ur = (float4*)(d_u + (size_t)n * 12);
        ur[0] = a0; ur[1] = a1; ur[2] = a2;
    }
}

// u'f16 = dis * u ; lane5 = (dis, 0)
__global__ void __launch_bounds__(256) k_scale() {
    int n = blockIdx.x * blockDim.x + threadIdx.x;
    if (n >= N_NODES) return;
    float dis = rsqrtf(d_deg[n] + 1.0f);
    const float4* ur = (const float4*)(d_u + (size_t)n * 12);
    float4 u0 = ur[0], u1 = ur[1], u2 = ur[2];
    unsigned* o = d_uf + (size_t)n * RW;
    o[0] = pack2(u0.x * dis, u0.y * dis);
    o[1] = pack2(u0.z * dis, u0.w * dis);
    o[2] = pack2(u1.x * dis, u1.y * dis);
    o[3] = pack2(u1.z * dis, u1.w * dis);
    o[4] = pack2(u2.x * dis, u2.y * dis);
    o[5] = pack2(dis, 0.0f);
}

// pass1: pure scatter-copy of u' rows into h1f (6 fp16x2 lanes)
__global__ void __launch_bounds__(256) k_pass1() {
    int e = blockIdx.x * blockDim.x + threadIdx.x;
    if (e >= N_EDGES) return;
    int2 rc = d_rc[e];
    const uint2* s = (const uint2*)(d_uf + (size_t)rc.x * RW);
    uint2 p0 = __ldg(&s[0]), p1 = __ldg(&s[1]), p2 = __ldg(&s[2]);
    unsigned* d = H1F + (size_t)rc.y * RW;
    redv2h(d,     p0.x, p0.y);
    redv2h(d + 2, p1.x, p1.y);
    redv2h(d + 4, p2.x, p2.y);
}

// post1: h1_full = dis*(S + u') + a1*bw ; write h1' = dis*h1_full (fp16)
__global__ void __launch_bounds__(256) k_post1() {
    __shared__ float sbw[NC];
    if (threadIdx.x < NC) sbw[threadIdx.x] = d_bw[threadIdx.x];
    __syncthreads();
    int n = blockIdx.x * blockDim.x + threadIdx.x;
    if (n >= N_NODES) return;
    float dis = rsqrtf(d_deg[n] + 1.0f);
    unsigned* hr = H1F + (size_t)n * RW;
    const unsigned* ur = d_uf + (size_t)n * RW;
    float S[NC], U[NC];
#pragma unroll
    for (int q = 0; q < 5; q++) {
        float2 sv = unpack2(hr[q]);
        float2 uv = unpack2(ur[q]);
        S[2*q] = sv.x; S[2*q+1] = sv.y;
        U[2*q] = uv.x; U[2*q+1] = uv.y;
    }
    float sumdis = unpack2(hr[5]).x;
    float a1 = dis * (sumdis + dis);
    d_a1[n] = a1;
#pragma unroll
    for (int c = 0; c < NC; c++) {
        float h = dis * (S[c] + U[c]) + a1 * sbw[c];
        S[c] = dis * h;                       // prescale for pass2
    }
#pragma unroll
    for (int q = 0; q < 5; q++) hr[q] = pack2(S[2*q], S[2*q+1]);
    hr[5] = 0u;
}

// pass2: scatter-copy h1' rows into h2f (5 fp16x2 lanes)
__global__ void __launch_bounds__(256) k_pass2() {
    int e = blockIdx.x * blockDim.x + threadIdx.x;
    if (e >= N_EDGES) return;
    int2 rc = d_rc[e];
    const uint2* s = (const uint2*)(H1F + (size_t)rc.x * RW);
    uint2 p0 = __ldg(&s[0]), p1 = __ldg(&s[1]), p2 = __ldg(&s[2]);
    unsigned* d = H2F + (size_t)rc.y * RW;
    redv2h(d,     p0.x, p0.y);
    redv2h(d + 2, p1.x, p1.y);
    redh(d + 4, p2.x);
}

// pool: val = dis*(T + h1') + a1*b2 ; per-graph mean-pool accumulate
__global__ void __launch_bounds__(256) k_pool(const void* batch, const float* __restrict__ b2) {
    __shared__ float sp[NG * NC];
    __shared__ float sc[NG];
    __shared__ float sb2[NC];
    int t = threadIdx.x;
    for (int j = t; j < NG * NC; j += 256) sp[j] = 0.0f;
    if (t < NG) sc[t] = 0.0f;
    if (t < NC) sb2[t] = b2[t];
    __syncthreads();
    int n = blockIdx.x * 256 + t;
    if (n < N_NODES) {
        int g = read_idx(batch, n, d_is64);
        float dis = rsqrtf(d_deg[n] + 1.0f);
        float a1 = d_a1[n];
        const unsigned* tr = H2F + (size_t)n * RW;
        const unsigned* qr = H1F + (size_t)n * RW;
#pragma unroll
        for (int q = 0; q < 5; q++) {
            float2 tv = unpack2(tr[q]);
            float2 qv = unpack2(qr[q]);
            float v0 = dis * (tv.x + qv.x) + a1 * sb2[2*q];
            float v1 = dis * (tv.y + qv.y) + a1 * sb2[2*q+1];
            atomicAdd(&sp[g * NC + 2*q],     v0);
            atomicAdd(&sp[g * NC + 2*q + 1], v1);
        }
        atomicAdd(&sc[g], 1.0f);
    }
    __syncthreads();
    for (int j = t; j < NG * NC; j += 256)
        if (sp[j] != 0.0f) atomicAdd(&d_pool[j], sp[j]);
    if (t < NG && sc[t] != 0.0f) atomicAdd(&d_gcnt[t], sc[t]);
}

// divide by counts, log_softmax
__global__ void __launch_bounds__(64) k_final(float* __restrict__ out) {
    int g = threadIdx.x;
    float inv = 1.0f / fmaxf(d_gcnt[g], 1.0f);
    float p[NC];
#pragma unroll
    for (int c = 0; c < NC; c++) p[c] = d_pool[g * NC + c] * inv;
    float mx = p[0];
#pragma unroll
    for (int c = 1; c < NC; c++) mx = fmaxf(mx, p[c]);
    float se = 0.0f;
#pragma unroll
    for (int c = 0; c < NC; c++) se += expf(p[c] - mx);
    float l = logf(se);
#pragma unroll
    for (int c = 0; c < NC; c++) out[g * NC + c] = p[c] - mx - l;
}

// ---------------- launch ----------------
extern "C" void kernel_launch(void* const* d_in, const int* in_sizes, int n_in,
                              void* d_out, int out_size) {
    const float* x = (const float*)d_in[0];
    const void*  ei = d_in[1];
    const void*  batch = d_in[2];
    int w = (in_sizes[3] == 1) ? 4 : 3;
    const float* W1 = (const float*)d_in[w + 0];
    const float* b1 = (const float*)d_in[w + 1];
    const float* W2 = (const float*)d_in[w + 2];
    const float* b2 = (const float*)d_in[w + 3];
    float* out = (float*)d_out;

    void* p;
    cudaGetSymbolAddress(&p, d_deg);  cudaMemsetAsync(p, 0, sizeof(float) * N_NODES);
    cudaGetSymbolAddress(&p, d_hf);   cudaMemsetAsync(p, 0, sizeof(unsigned) * 2 * N_NODES * RW);
    cudaGetSymbolAddress(&p, d_pool); cudaMemsetAsync(p, 0, sizeof(float) * NG * NC);
    cudaGetSymbolAddress(&p, d_gcnt); cudaMemsetAsync(p, 0, sizeof(float) * NG);

    k_init<<<2, 128>>>(ei, W1, W2, b1);
    k_fat <<<PACK_BLOCKS + U_BLOCKS, 256>>>(ei, x);
    k_scale<<<(N_NODES + 255) / 256, 256>>>();

    k_pass1<<<(N_EDGES + 255) / 256, 256>>>();
    k_post1<<<(N_NODES + 255) / 256, 256>>>();
    k_pass2<<<(N_EDGES + 255) / 256, 256>>>();

    k_pool<<<(N_NODES + 255) / 256, 256>>>(batch, b2);
    k_final<<<1, NG>>>(out);
}

// round 9
// speedup vs baseline: 2.9718x; 1.0847x over previous
#include <cuda_runtime.h>
#include <cuda_fp16.h>
#include <cstdint>

#define N_NODES 100000
#define N_EDGES 1600000
#define NF 128
#define NC 10
#define NG 64
#define RW 8   // half2 lanes per row: 5 class lanes + aux lane + 2 pad = 32B sector

#define PACK_BLOCKS ((N_EDGES + 255) / 256)   // 6250
#define U_BLOCKS    ((N_NODES + 255) / 256)   // 391

// ---------------- scratch ----------------
__device__ __align__(32) float    d_deg[N_NODES];        // edge-only degree
__device__ __align__(16) int2     d_rc[N_EDGES];
__device__ __align__(16) float    d_u [N_NODES * 12];    // x @ Wc (f32, 12-wide)
__device__ __align__(32) unsigned d_uf[N_NODES * RW];    // dis*u fp16x2; lane5 = (dis,0)
__device__ __align__(32) unsigned d_hf[2 * N_NODES * RW]; // [h1f | h2f]
__device__ __align__(16) float    d_a1[N_NODES];
__device__ __align__(16) float    d_Wc[NF * 12];
__device__ __align__(16) float    d_bw[12];
__device__ float d_pool[NG * NC];
__device__ float d_gcnt[NG];
__device__ int   d_is64;

#define H1F d_hf
#define H2F (d_hf + N_NODES * RW)

// ---------------- helpers ----------------
__device__ __forceinline__ int read_idx(const void* p, long long i, int is64) {
    return is64 ? (int)((const long long*)p)[i] : ((const int*)p)[i];
}
__device__ __forceinline__ void redv4h(unsigned* addr, uint4 v) {
    asm volatile("red.global.add.noftz.v4.f16x2 [%0], {%1,%2,%3,%4};"
                 :: "l"(addr), "r"(v.x), "r"(v.y), "r"(v.z), "r"(v.w) : "memory");
}
__device__ __forceinline__ void redv2h(unsigned* addr, unsigned a, unsigned b) {
    asm volatile("red.global.add.noftz.v2.f16x2 [%0], {%1,%2};"
                 :: "l"(addr), "r"(a), "r"(b) : "memory");
}
__device__ __forceinline__ void redh(unsigned* addr, unsigned a) {
    asm volatile("red.global.add.noftz.f16x2 [%0], %1;"
                 :: "l"(addr), "r"(a) : "memory");
}
__device__ __forceinline__ unsigned pack2(float lo, float hi) {
    __half2 h = __floats2half2_rn(lo, hi);
    return *reinterpret_cast<unsigned*>(&h);
}
__device__ __forceinline__ float2 unpack2(unsigned u) {
    __half2 h = *reinterpret_cast<__half2*>(&u);
    return make_float2(__low2float(h), __high2float(h));
}

// detect int64 indices (block 0) + Wc = W1@W2, bw = b1@W2 (block 1)
__global__ void __launch_bounds__(128) k_init(const void* ei,
                                              const float* __restrict__ W1,
                                              const float* __restrict__ W2,
                                              const float* __restrict__ b1) {
    if (blockIdx.x == 0) {
        if (threadIdx.x < 32) {
            const int* p = (const int*)ei;
            unsigned ok = __ballot_sync(0xFFFFFFFFu, p[2 * threadIdx.x + 1] == 0);
            if (threadIdx.x == 0) d_is64 = (ok == 0xFFFFFFFFu) ? 1 : 0;
        }
        return;
    }
    __shared__ float sW2[NF * NC];
    int t = threadIdx.x;                       // t = input-feature row
    for (int j = t; j < NF * NC; j += NF) sW2[j] = W2[j];
    __syncthreads();
    float acc[NC];
#pragma unroll
    for (int c = 0; c < NC; c++) acc[c] = 0.0f;
    for (int f = 0; f < NF; f++) {
        float w = W1[t * NF + f];
#pragma unroll
        for (int c = 0; c < NC; c++) acc[c] += w * sW2[f * NC + c];
    }
#pragma unroll
    for (int c = 0; c < NC; c++) d_Wc[t * 12 + c] = acc[c];
    d_Wc[t * 12 + 10] = 0.0f; d_Wc[t * 12 + 11] = 0.0f;
    if (t < NC) {
        float a = 0.0f;
        for (int f = 0; f < NF; f++) a += b1[f] * sW2[f * NC + t];
        d_bw[t] = a;
    }
    if (t == 0) { d_bw[10] = 0.0f; d_bw[11] = 0.0f; }
}

// Fat: blocks [0,PACK) pack rc + degree atomics; trailing blocks u = x @ Wc (f32)
__global__ void __launch_bounds__(256) k_fat(const void* ei, const float* __restrict__ x) {
    if (blockIdx.x < PACK_BLOCKS) {
        int e = blockIdx.x * 256 + threadIdx.x;
        if (e >= N_EDGES) return;
        int is64 = d_is64;
        int r = read_idx(ei, e, is64);
        int c = read_idx(ei, (long long)N_EDGES + e, is64);
        d_rc[e] = make_int2(r, c);
        atomicAdd(&d_deg[c], 1.0f);
    } else {
        __shared__ float4 sWc[NF * 3];
        int t = threadIdx.x;
        for (int j = t; j < NF * 3; j += 256) sWc[j] = ((const float4*)d_Wc)[j];
        __syncthreads();
        int n = (blockIdx.x - PACK_BLOCKS) * 256 + t;
        if (n >= N_NODES) return;
        float4 a0 = make_float4(0,0,0,0), a1 = a0, a2 = a0;
        const float4* xr = (const float4*)(x + (size_t)n * NF);
#pragma unroll 4
        for (int k4 = 0; k4 < NF / 4; k4++) {
            float4 xv = __ldg(&xr[k4]);
#pragma unroll
            for (int kk = 0; kk < 4; kk++) {
                float s = (kk == 0) ? xv.x : (kk == 1) ? xv.y : (kk == 2) ? xv.z : xv.w;
                int k = k4 * 4 + kk;
                float4 w0 = sWc[k * 3 + 0], w1 = sWc[k * 3 + 1], w2 = sWc[k * 3 + 2];
                a0.x += s * w0.x; a0.y += s * w0.y; a0.z += s * w0.z; a0.w += s * w0.w;
                a1.x += s * w1.x; a1.y += s * w1.y; a1.z += s * w1.z; a1.w += s * w1.w;
                a2.x += s * w2.x; a2.y += s * w2.y; a2.z += s * w2.z; a2.w += s * w2.w;
            }
        }
        float4* ur = (float4*)(d_u + (size_t)n * 12);
        ur[0] = a0; ur[1] = a1; ur[2] = a2;
    }
}

// u'f16 = dis * u ; lane5 = (dis, 0); lanes 6,7 = 0
__global__ void __launch_bounds__(256) k_scale() {
    int n = blockIdx.x * blockDim.x + threadIdx.x;
    if (n >= N_NODES) return;
    float dis = rsqrtf(d_deg[n] + 1.0f);
    const float4* ur = (const float4*)(d_u + (size_t)n * 12);
    float4 u0 = ur[0], u1 = ur[1], u2 = ur[2];
    uint4* o = (uint4*)(d_uf + (size_t)n * RW);
    o[0] = make_uint4(pack2(u0.x * dis, u0.y * dis),
                      pack2(u0.z * dis, u0.w * dis),
                      pack2(u1.x * dis, u1.y * dis),
                      pack2(u1.z * dis, u1.w * dis));
    o[1] = make_uint4(pack2(u2.x * dis, u2.y * dis),
                      pack2(dis, 0.0f), 0u, 0u);
}

// pass1: scatter-copy u' rows into h1f: one v4 RED + one v2 RED (lanes 0-5)
__global__ void __launch_bounds__(256) k_pass1() {
    int e = blockIdx.x * blockDim.x + threadIdx.x;
    if (e >= N_EDGES) return;
    int2 rc = __ldg(&d_rc[e]);
    const uint4* s = (const uint4*)(d_uf + (size_t)rc.x * RW);
    uint4 p0 = __ldg(&s[0]);
    uint4 p1 = __ldg(&s[1]);                  // .x=lane4, .y=lane5(dis)
    unsigned* d = H1F + (size_t)rc.y * RW;
    redv4h(d, p0);
    redv2h(d + 4, p1.x, p1.y);
}

// post1: h1_full = dis*(S + u') + a1*bw ; write h1' = dis*h1_full (fp16), lane5=0
__global__ void __launch_bounds__(256) k_post1() {
    __shared__ float sbw[NC];
    if (threadIdx.x < NC) sbw[threadIdx.x] = d_bw[threadIdx.x];
    __syncthreads();
    int n = blockIdx.x * blockDim.x + threadIdx.x;
    if (n >= N_NODES) return;
    float dis = rsqrtf(d_deg[n] + 1.0f);
    uint4* hr = (uint4*)(H1F + (size_t)n * RW);
    const uint4* ur = (const uint4*)(d_uf + (size_t)n * RW);
    uint4 h0 = hr[0], h1 = hr[1];
    uint4 u0 = ur[0], u1 = ur[1];
    float S[NC], U[NC];
    {
        float2 a, b;
        a = unpack2(h0.x); S[0]=a.x; S[1]=a.y;  a = unpack2(h0.y); S[2]=a.x; S[3]=a.y;
        a = unpack2(h0.z); S[4]=a.x; S[5]=a.y;  a = unpack2(h0.w); S[6]=a.x; S[7]=a.y;
        a = unpack2(h1.x); S[8]=a.x; S[9]=a.y;
        b = unpack2(u0.x); U[0]=b.x; U[1]=b.y;  b = unpack2(u0.y); U[2]=b.x; U[3]=b.y;
        b = unpack2(u0.z); U[4]=b.x; U[5]=b.y;  b = unpack2(u0.w); U[6]=b.x; U[7]=b.y;
        b = unpack2(u1.x); U[8]=b.x; U[9]=b.y;
    }
    float sumdis = unpack2(h1.y).x;
    float a1 = dis * (sumdis + dis);
    d_a1[n] = a1;
#pragma unroll
    for (int c = 0; c < NC; c++) {
        float h = dis * (S[c] + U[c]) + a1 * sbw[c];
        S[c] = dis * h;                       // prescale for pass2
    }
    hr[0] = make_uint4(pack2(S[0],S[1]), pack2(S[2],S[3]), pack2(S[4],S[5]), pack2(S[6],S[7]));
    hr[1] = make_uint4(pack2(S[8],S[9]), 0u, 0u, 0u);
}

// pass2: scatter-copy h1' rows into h2f: one v4 RED + one scalar RED (lanes 0-4)
__global__ void __launch_bounds__(256) k_pass2() {
    int e = blockIdx.x * blockDim.x + threadIdx.x;
    if (e >= N_EDGES) return;
    int2 rc = __ldg(&d_rc[e]);
    const uint4* s = (const uint4*)(H1F + (size_t)rc.x * RW);
    uint4 p0 = __ldg(&s[0]);
    unsigned p4 = __ldg((const unsigned*)&s[1]);   // lane4
    unsigned* d = H2F + (size_t)rc.y * RW;
    redv4h(d, p0);
    redh(d + 4, p4);
}

// pool: val = dis*(T + h1') + a1*b2 ; per-graph mean-pool accumulate
__global__ void __launch_bounds__(256) k_pool(const void* batch, const float* __restrict__ b2) {
    __shared__ float sp[NG * NC];
    __shared__ float sc[NG];
    __shared__ float sb2[NC];
    int t = threadIdx.x;
    for (int j = t; j < NG * NC; j += 256) sp[j] = 0.0f;
    if (t < NG) sc[t] = 0.0f;
    if (t < NC) sb2[t] = b2[t];
    __syncthreads();
    int n = blockIdx.x * 256 + t;
    if (n < N_NODES) {
        int g = read_idx(batch, n, d_is64);
        float dis = rsqrtf(d_deg[n] + 1.0f);
        float a1 = d_a1[n];
        const unsigned* tr = H2F + (size_t)n * RW;
        const unsigned* qr = H1F + (size_t)n * RW;
#pragma unroll
        for (int q = 0; q < 5; q++) {
            float2 tv = unpack2(tr[q]);
            float2 qv = unpack2(qr[q]);
            float v0 = dis * (tv.x + qv.x) + a1 * sb2[2*q];
            float v1 = dis * (tv.y + qv.y) + a1 * sb2[2*q+1];
            atomicAdd(&sp[g * NC + 2*q],     v0);
            atomicAdd(&sp[g * NC + 2*q + 1], v1);
        }
        atomicAdd(&sc[g], 1.0f);
    }
    __syncthreads();
    for (int j = t; j < NG * NC; j += 256)
        if (sp[j] != 0.0f) atomicAdd(&d_pool[j], sp[j]);
    if (t < NG && sc[t] != 0.0f) atomicAdd(&d_gcnt[t], sc[t]);
}

// divide by counts, log_softmax
__global__ void __launch_bounds__(64) k_final(float* __restrict__ out) {
    int g = threadIdx.x;
    float inv = 1.0f / fmaxf(d_gcnt[g], 1.0f);
    float p[NC];
#pragma unroll
    for (int c = 0; c < NC; c++) p[c] = d_pool[g * NC + c] * inv;
    float mx = p[0];
#pragma unroll
    for (int c = 1; c < NC; c++) mx = fmaxf(mx, p[c]);
    float se = 0.0f;
#pragma unroll
    for (int c = 0; c < NC; c++) se += expf(p[c] - mx);
    float l = logf(se);
#pragma unroll
    for (int c = 0; c < NC; c++) out[g * NC + c] = p[c] - mx - l;
}

// ---------------- launch ----------------
extern "C" void kernel_launch(void* const* d_in, const int* in_sizes, int n_in,
                              void* d_out, int out_size) {
    const float* x = (const float*)d_in[0];
    const void*  ei = d_in[1];
    const void*  batch = d_in[2];
    int w = (in_sizes[3] == 1) ? 4 : 3;
    const float* W1 = (const float*)d_in[w + 0];
    const float* b1 = (const float*)d_in[w + 1];
    const float* W2 = (const float*)d_in[w + 2];
    const float* b2 = (const float*)d_in[w + 3];
    float* out = (float*)d_out;

    void* p;
    cudaGetSymbolAddress(&p, d_deg);  cudaMemsetAsync(p, 0, sizeof(float) * N_NODES);
    cudaGetSymbolAddress(&p, d_hf);   cudaMemsetAsync(p, 0, sizeof(unsigned) * 2 * N_NODES * RW);
    cudaGetSymbolAddress(&p, d_pool); cudaMemsetAsync(p, 0, sizeof(float) * NG * NC);
    cudaGetSymbolAddress(&p, d_gcnt); cudaMemsetAsync(p, 0, sizeof(float) * NG);

    k_init<<<2, 128>>>(ei, W1, W2, b1);
    k_fat <<<PACK_BLOCKS + U_BLOCKS, 256>>>(ei, x);
    k_scale<<<(N_NODES + 255) / 256, 256>>>();

    k_pass1<<<(N_EDGES + 255) / 256, 256>>>();
    k_post1<<<(N_NODES + 255) / 256, 256>>>();
    k_pass2<<<(N_EDGES + 255) / 256, 256>>>();

    k_pool<<<(N_NODES + 255) / 256, 256>>>(batch, b2);
    k_final<<<1, NG>>>(out);
}